// round 12
// baseline (speedup 1.0000x reference)
#include <cuda_runtime.h>
#include <cstdint>

// D-FPS (B=8, N=32768, npoint=2048) + gather xyz -> out (B,3,2048) fp32.
//
// One 8-CTA cluster per batch (64 CTAs, 128 threads = 4 warps). Each thread
// owns 32 points, PACKED f32x2 in registers; running-min temp in registers.
// Per iteration (NO cluster barrier in the loop):
//   - packed add/mul.rn.f32x2 distance update (per-lane .rn => bit-exact)
//   - warp argmax via redux.sync (float bits of v>=0 are u32-monotone),
//     min-index tie-break == jnp.argmax first-occurrence
//   - CTA argmax in warp0 via redux; lanes 0..7 push {key,x,y,z} to cluster
//     CTA dst==lane in parallel (mapa + st.shared::cluster), then release a
//     TAG word (value=j) via st.release.cluster -- orders the data stores
//   - ALL threads poll the 8 local tags (two ld.volatile.shared.v4.u32 per
//     round, broadcast reads) until all == j, then one fence.acq_rel.cluster
//   - every thread picks the cluster winner via a depth-3 max tree.
// Reuse safety (parity-buffered slots + tags): y's iter-j slot reads precede
// y's syncA(j+1), which precedes y-leader's release tag j+1, which is
// acquire-observed by x during iter j+1, which precedes x's syncA(j+2) and
// x's same-parity overwrite at j+2. Tags monotone; zero-init + one startup
// cluster barrier; final cluster barrier for exit safety.

constexpr int BATCH   = 8;
constexpr int NPTS    = 32768;
constexpr int NPOINT  = 2048;
constexpr int CLUSTER = 8;
constexpr int T       = 128;
constexpr int PER_CTA = NPTS / CLUSTER;  // 4096
constexpr int P       = PER_CTA / T;     // 32 points / thread
constexpr int NPAIR   = P / 2;           // 16 packed pairs
constexpr int NW      = T / 32;          // 4 warps

__device__ __forceinline__ uint32_t smem_u32(const void* p) {
    uint32_t a;
    asm("{ .reg .u64 t; cvta.to.shared.u64 t, %1; cvt.u32.u64 %0, t; }"
        : "=r"(a) : "l"(p));
    return a;
}

extern __shared__ float s_dyn[];  // sx[4096] | sy[4096] | sz[4096] = 48KB

__global__ __launch_bounds__(T, 1) __cluster_dims__(CLUSTER, 1, 1)
void fps_cluster_kernel(const float* __restrict__ xyz_t, float* __restrict__ out)
{
    const int b = blockIdx.x >> 3;
    uint32_t rank;
    asm("mov.u32 %0, %%cluster_ctarank;" : "=r"(rank));

    const float* __restrict__ xs = xyz_t + (size_t)b * 3 * NPTS;
    const float* __restrict__ ys = xs + NPTS;
    const float* __restrict__ zs = xs + 2 * NPTS;
    float* __restrict__ ob = out + (size_t)b * 3 * NPOINT;

    const int tid = threadIdx.x;
    const int w = tid >> 5, l = tid & 31;
    const int pbase = (int)rank * PER_CTA;

    float* sx = s_dyn;
    float* sy = s_dyn + PER_CTA;
    float* sz = s_dyn + 2 * PER_CTA;

    __shared__ uint32_t s_wv[NW], s_wi[NW];
    __shared__ unsigned long long s_key[2][CLUSTER];
    __shared__ float4 s_co[2][CLUSTER];
    __shared__ __align__(16) uint32_t s_tag[2][CLUSTER];

    // ---- load coords: smem table + packed registers ----
    unsigned long long xp[NPAIR], yp[NPAIR], zp[NPAIR];
    float tmp[P];
#pragma unroll
    for (int q = 0; q < NPAIR; ++q) {
        const int g0 = pbase + (2 * q)     * T + tid;
        const int g1 = pbase + (2 * q + 1) * T + tid;
        const float ax0 = xs[g0], ax1 = xs[g1];
        const float ay0 = ys[g0], ay1 = ys[g1];
        const float az0 = zs[g0], az1 = zs[g1];
        sx[(2*q)   * T + tid] = ax0;  sx[(2*q+1) * T + tid] = ax1;
        sy[(2*q)   * T + tid] = ay0;  sy[(2*q+1) * T + tid] = ay1;
        sz[(2*q)   * T + tid] = az0;  sz[(2*q+1) * T + tid] = az1;
        asm("mov.b64 %0, {%1, %2};" : "=l"(xp[q]) : "f"(ax0), "f"(ax1));
        asm("mov.b64 %0, {%1, %2};" : "=l"(yp[q]) : "f"(ay0), "f"(ay1));
        asm("mov.b64 %0, {%1, %2};" : "=l"(zp[q]) : "f"(az0), "f"(az1));
        tmp[2*q] = 1e10f; tmp[2*q+1] = 1e10f;
    }
    if (tid < 2 * CLUSTER) s_tag[tid >> 3][tid & 7] = 0u;

    // tags must be zero cluster-wide before any remote release-store
    asm volatile("barrier.cluster.arrive.aligned;" ::: "memory");
    asm volatile("barrier.cluster.wait.aligned;" ::: "memory");

    float lx = __ldg(xs), ly = __ldg(ys), lz = __ldg(zs);  // idx[0] = 0
    if (rank == 0 && tid == 0) {
        ob[0] = lx; ob[NPOINT] = ly; ob[2 * NPOINT] = lz;
    }

    const uint32_t tag0_a = smem_u32(&s_tag[0][0]);
    const uint32_t tag1_a = smem_u32(&s_tag[1][0]);

    for (int j = 1; j < NPOINT; ++j) {
        // packed negated center (per-lane duplicate)
        unsigned long long nlx2, nly2, nlz2;
        {
            const float nx = -lx, ny = -ly, nz = -lz;
            asm("mov.b64 %0, {%1, %1};" : "=l"(nlx2) : "f"(nx));
            asm("mov.b64 %0, {%1, %1};" : "=l"(nly2) : "f"(ny));
            asm("mov.b64 %0, {%1, %1};" : "=l"(nlz2) : "f"(nz));
        }

        float bv = -1.0f;
        int   bs = 0;
#pragma unroll
        for (int q = 0; q < NPAIR; ++q) {
            unsigned long long dx, dy, dz, qx, qy, qz, s01, acc;
            asm("add.rn.f32x2 %0, %1, %2;" : "=l"(dx) : "l"(xp[q]), "l"(nlx2));
            asm("add.rn.f32x2 %0, %1, %2;" : "=l"(dy) : "l"(yp[q]), "l"(nly2));
            asm("add.rn.f32x2 %0, %1, %2;" : "=l"(dz) : "l"(zp[q]), "l"(nlz2));
            asm("mul.rn.f32x2 %0, %1, %1;" : "=l"(qx) : "l"(dx));
            asm("mul.rn.f32x2 %0, %1, %1;" : "=l"(qy) : "l"(dy));
            asm("mul.rn.f32x2 %0, %1, %1;" : "=l"(qz) : "l"(dz));
            asm("add.rn.f32x2 %0, %1, %2;" : "=l"(s01) : "l"(qx), "l"(qy));
            asm("add.rn.f32x2 %0, %1, %2;" : "=l"(acc) : "l"(s01), "l"(qz));
            float d0, d1;
            asm("mov.b64 {%0, %1}, %2;" : "=f"(d0), "=f"(d1) : "l"(acc));
            float t0 = fminf(tmp[2*q], d0);     tmp[2*q] = t0;
            if (t0 > bv) { bv = t0; bs = 2*q; }
            float t1 = fminf(tmp[2*q+1], d1);   tmp[2*q+1] = t1;
            if (t1 > bv) { bv = t1; bs = 2*q+1; }
        }
        const uint32_t idx = (uint32_t)(pbase + bs * T + tid);

        // ---- warp argmax via redux (float bits of v>=0 are u32-monotone) ----
        const uint32_t vb   = __float_as_uint(bv);
        const uint32_t vmax = __reduce_max_sync(0xffffffffu, vb);
        const uint32_t imin = __reduce_min_sync(0xffffffffu,
                                   (vb == vmax) ? idx : 0xffffffffu);
        if (l == 0) { s_wv[w] = vmax; s_wi[w] = imin; }
        __syncthreads();   // sync A: warp candidates visible; anchors the
                           // happens-before chain for slot reuse

        const int p = j & 1;

        if (w == 0) {
            const uint32_t v  = (l < NW) ? s_wv[l] : 0u;
            const uint32_t ii = (l < NW) ? s_wi[l] : 0xffffffffu;
            const uint32_t vm = __reduce_max_sync(0xffffffffu, v);
            const uint32_t im = __reduce_min_sync(0xffffffffu,
                                    (v == vm) ? ii : 0xffffffffu);
            // lanes 0..7 disseminate to cluster CTA dst == lane, in parallel
            if (l < CLUSTER) {
                const int li = (int)im - pbase;      // winner is in own range
                const float cx = sx[li], cy = sy[li], cz = sz[li];  // LDS bcast
                const unsigned long long key =
                    ((unsigned long long)vm << 32) | (uint32_t)(~im);
                unsigned long long xyp;
                asm("mov.b64 %0, {%1, %2};" : "=l"(xyp) : "f"(cx), "f"(cy));
                const uint32_t zb = __float_as_uint(cz);
                const uint32_t ka = smem_u32(&s_key[p][rank]);
                const uint32_t ca = smem_u32(&s_co[p][rank]);
                const uint32_t ta = smem_u32(&s_tag[p][rank]);
                const int dco = (int)(ca - ka);
                const int dta = (int)(ta - ka);
                uint32_t rk;
                asm volatile("mapa.shared::cluster.u32 %0, %1, %2;"
                             : "=r"(rk) : "r"(ka), "r"(l));
                asm volatile("st.shared::cluster.b64 [%0], %1;"
                             :: "r"(rk), "l"(key) : "memory");
                asm volatile("st.shared::cluster.b64 [%0], %1;"
                             :: "r"(rk + dco), "l"(xyp) : "memory");
                asm volatile("st.shared::cluster.b32 [%0+8], %1;"
                             :: "r"(rk + dco), "r"(zb) : "memory");
                // release: orders the three data stores before the tag
                asm volatile("st.release.cluster.shared::cluster.u32 [%0], %1;"
                             :: "r"(rk + dta), "r"((uint32_t)j) : "memory");
            }
        }

        // ---- every thread polls the 8 local tags until all == j ----
        {
            const uint32_t ta = p ? tag1_a : tag0_a;
            uint32_t a0, a1, a2, a3, b0, b1, b2, b3;
            do {
                asm volatile("ld.volatile.shared.v4.u32 {%0,%1,%2,%3}, [%4];"
                             : "=r"(a0), "=r"(a1), "=r"(a2), "=r"(a3)
                             : "r"(ta));
                asm volatile("ld.volatile.shared.v4.u32 {%0,%1,%2,%3}, [%4+16];"
                             : "=r"(b0), "=r"(b1), "=r"(b2), "=r"(b3)
                             : "r"(ta));
            } while ((a0 & a1 & a2 & a3 & b0 & b1 & b2 & b3) != (uint32_t)j ||
                     (a0 | a1 | a2 | a3 | b0 | b1 | b2 | b3) != (uint32_t)j);
            asm volatile("fence.acq_rel.cluster;" ::: "memory");
        }

        // ---- pick cluster winner: depth-3 max tree over 8 slots ----
        {
            unsigned long long k0 = s_key[p][0], k1 = s_key[p][1];
            unsigned long long k2 = s_key[p][2], k3 = s_key[p][3];
            unsigned long long k4 = s_key[p][4], k5 = s_key[p][5];
            unsigned long long k6 = s_key[p][6], k7 = s_key[p][7];
            int c0 = 0, c2 = 2, c4 = 4, c6 = 6;
            if (k1 > k0) { k0 = k1; c0 = 1; }
            if (k3 > k2) { k2 = k3; c2 = 3; }
            if (k5 > k4) { k4 = k5; c4 = 5; }
            if (k7 > k6) { k6 = k7; c6 = 7; }
            if (k2 > k0) { k0 = k2; c0 = c2; }
            if (k6 > k4) { k4 = k6; c4 = c6; }
            if (k4 > k0) { k0 = k4; c0 = c4; }
            const float4 co = s_co[p][c0];
            lx = co.x; ly = co.y; lz = co.z;
        }

        if (rank == 0 && tid == 0) {
            ob[j]              = lx;
            ob[NPOINT + j]     = ly;
            ob[2 * NPOINT + j] = lz;
        }
    }

    // no CTA may exit while peers may still target its smem
    asm volatile("barrier.cluster.arrive.aligned;" ::: "memory");
    asm volatile("barrier.cluster.wait.aligned;" ::: "memory");
}

extern "C" void kernel_launch(void* const* d_in, const int* in_sizes, int n_in,
                              void* d_out, int out_size)
{
    (void)in_sizes; (void)n_in; (void)out_size;
    const float* xyz_t = (const float*)d_in[1];   // points_xyz_t: (B, 3, N)
    float* out = (float*)d_out;                   // (B, 3, NPOINT)

    // Opt in to >48KB-total smem (48KB dynamic + ~0.4KB static). Host-side
    // attribute call: nothing enqueued on the stream, capture-safe,
    // deterministic and idempotent.
    const int dyn_bytes = 3 * PER_CTA * (int)sizeof(float);   // 49152
    cudaFuncSetAttribute(fps_cluster_kernel,
                         cudaFuncAttributeMaxDynamicSharedMemorySize, dyn_bytes);

    fps_cluster_kernel<<<BATCH * CLUSTER, T, dyn_bytes>>>(xyz_t, out);
}

// round 13
// speedup vs baseline: 1.4325x; 1.4325x over previous
#include <cuda_runtime.h>
#include <cstdint>

// D-FPS (B=8, N=32768, npoint=2048) + gather xyz -> out (B,3,2048) fp32.
//
// One 8-CTA cluster per batch (64 CTAs, 128 threads = 4 warps). Each thread
// owns 32 points, PACKED f32x2 in registers; running-min temp in registers.
// Per iteration (NO __syncthreads in the loop):
//   - packed add/mul.rn.f32x2 distance update (per-lane .rn => bit-exact)
//   - warp argmax via redux.sync (float bits of v>=0 are u32-monotone),
//     min-index tie-break == jnp.argmax first-occurrence
//   - EVERY warp pushes its warp candidate {key, x,y,z} to all 8 cluster
//     CTAs (lanes 0..7 -> dst==lane, slot = rank*4 + warp); coords from the
//     CTA-local smem coord table (broadcast LDS)
//   - ONE barrier.cluster (arrive releases the remote stores, wait acquires;
//     it is the only synchronization -- no CTA barrier needed)
//   - warp-parallel pick over the 32 cluster-wide candidates: lane l loads
//     key[l], redux max on value bits + redux min on index (tie-break),
//     ballot+ffs -> winner slot (keys are globally unique, exactly one bit),
//     one broadcast LDS.128 for the winner coords.
// Slots double-buffered by parity: reads of parity-p slots at iter j precede
// the reader's arrive at barrier j+1, which precedes any writer's same-parity
// overwrite at iter j+2 (issued only after its barrier-(j+1) wait).

constexpr int BATCH   = 8;
constexpr int NPTS    = 32768;
constexpr int NPOINT  = 2048;
constexpr int CLUSTER = 8;
constexpr int T       = 128;
constexpr int PER_CTA = NPTS / CLUSTER;  // 4096
constexpr int P       = PER_CTA / T;     // 32 points / thread
constexpr int NPAIR   = P / 2;           // 16 packed pairs
constexpr int NW      = T / 32;          // 4 warps
constexpr int NSLOT   = CLUSTER * NW;    // 32 cluster-wide candidates

__device__ __forceinline__ uint32_t smem_u32(const void* p) {
    uint32_t a;
    asm("{ .reg .u64 t; cvta.to.shared.u64 t, %1; cvt.u32.u64 %0, t; }"
        : "=r"(a) : "l"(p));
    return a;
}

extern __shared__ float s_dyn[];  // sx[4096] | sy[4096] | sz[4096] = 48KB

__global__ __launch_bounds__(T, 1) __cluster_dims__(CLUSTER, 1, 1)
void fps_cluster_kernel(const float* __restrict__ xyz_t, float* __restrict__ out)
{
    const int b = blockIdx.x >> 3;
    uint32_t rank;
    asm("mov.u32 %0, %%cluster_ctarank;" : "=r"(rank));

    const float* __restrict__ xs = xyz_t + (size_t)b * 3 * NPTS;
    const float* __restrict__ ys = xs + NPTS;
    const float* __restrict__ zs = xs + 2 * NPTS;
    float* __restrict__ ob = out + (size_t)b * 3 * NPOINT;

    const int tid = threadIdx.x;
    const int w = tid >> 5, l = tid & 31;
    const int pbase = (int)rank * PER_CTA;

    float* sx = s_dyn;
    float* sy = s_dyn + PER_CTA;
    float* sz = s_dyn + 2 * PER_CTA;

    __shared__ unsigned long long s_key[2][NSLOT];
    __shared__ float4 s_co[2][NSLOT];

    // ---- load coords: smem table + packed registers ----
    unsigned long long xp[NPAIR], yp[NPAIR], zp[NPAIR];
    float tmp[P];
#pragma unroll
    for (int q = 0; q < NPAIR; ++q) {
        const int g0 = pbase + (2 * q)     * T + tid;
        const int g1 = pbase + (2 * q + 1) * T + tid;
        const float ax0 = xs[g0], ax1 = xs[g1];
        const float ay0 = ys[g0], ay1 = ys[g1];
        const float az0 = zs[g0], az1 = zs[g1];
        sx[(2*q)   * T + tid] = ax0;  sx[(2*q+1) * T + tid] = ax1;
        sy[(2*q)   * T + tid] = ay0;  sy[(2*q+1) * T + tid] = ay1;
        sz[(2*q)   * T + tid] = az0;  sz[(2*q+1) * T + tid] = az1;
        asm("mov.b64 %0, {%1, %2};" : "=l"(xp[q]) : "f"(ax0), "f"(ax1));
        asm("mov.b64 %0, {%1, %2};" : "=l"(yp[q]) : "f"(ay0), "f"(ay1));
        asm("mov.b64 %0, {%1, %2};" : "=l"(zp[q]) : "f"(az0), "f"(az1));
        tmp[2*q] = 1e10f; tmp[2*q+1] = 1e10f;
    }

    float lx = __ldg(xs), ly = __ldg(ys), lz = __ldg(zs);  // idx[0] = 0
    if (rank == 0 && tid == 0) {
        ob[0] = lx; ob[NPOINT] = ly; ob[2 * NPOINT] = lz;
    }

    // DSMEM safety: peers fully launched + smem tables complete before any
    // remote store / before peers may read (also orders nothing else needed).
    asm volatile("barrier.cluster.arrive.aligned;" ::: "memory");
    asm volatile("barrier.cluster.wait.aligned;" ::: "memory");

    for (int j = 1; j < NPOINT; ++j) {
        // packed negated center (per-lane duplicate)
        unsigned long long nlx2, nly2, nlz2;
        {
            const float nx = -lx, ny = -ly, nz = -lz;
            asm("mov.b64 %0, {%1, %1};" : "=l"(nlx2) : "f"(nx));
            asm("mov.b64 %0, {%1, %1};" : "=l"(nly2) : "f"(ny));
            asm("mov.b64 %0, {%1, %1};" : "=l"(nlz2) : "f"(nz));
        }

        float bv = -1.0f;
        int   bs = 0;
#pragma unroll
        for (int q = 0; q < NPAIR; ++q) {
            unsigned long long dx, dy, dz, qx, qy, qz, s01, acc;
            asm("add.rn.f32x2 %0, %1, %2;" : "=l"(dx) : "l"(xp[q]), "l"(nlx2));
            asm("add.rn.f32x2 %0, %1, %2;" : "=l"(dy) : "l"(yp[q]), "l"(nly2));
            asm("add.rn.f32x2 %0, %1, %2;" : "=l"(dz) : "l"(zp[q]), "l"(nlz2));
            asm("mul.rn.f32x2 %0, %1, %1;" : "=l"(qx) : "l"(dx));
            asm("mul.rn.f32x2 %0, %1, %1;" : "=l"(qy) : "l"(dy));
            asm("mul.rn.f32x2 %0, %1, %1;" : "=l"(qz) : "l"(dz));
            asm("add.rn.f32x2 %0, %1, %2;" : "=l"(s01) : "l"(qx), "l"(qy));
            asm("add.rn.f32x2 %0, %1, %2;" : "=l"(acc) : "l"(s01), "l"(qz));
            float d0, d1;
            asm("mov.b64 {%0, %1}, %2;" : "=f"(d0), "=f"(d1) : "l"(acc));
            float t0 = fminf(tmp[2*q], d0);     tmp[2*q] = t0;
            if (t0 > bv) { bv = t0; bs = 2*q; }
            float t1 = fminf(tmp[2*q+1], d1);   tmp[2*q+1] = t1;
            if (t1 > bv) { bv = t1; bs = 2*q+1; }
        }
        const uint32_t idx = (uint32_t)(pbase + bs * T + tid);

        // ---- warp argmax via redux (float bits of v>=0 are u32-monotone) ----
        const uint32_t vb   = __float_as_uint(bv);
        const uint32_t vmax = __reduce_max_sync(0xffffffffu, vb);
        const uint32_t imin = __reduce_min_sync(0xffffffffu,
                                   (vb == vmax) ? idx : 0xffffffffu);

        const int p = j & 1;
        const int myslot = (int)rank * NW + w;

        // ---- every warp pushes its candidate to all 8 CTAs (lanes 0..7) ----
        if (l < CLUSTER) {
            const int li = (int)imin - pbase;        // in own range
            const float cx = sx[li], cy = sy[li], cz = sz[li];  // LDS bcast
            const unsigned long long key =
                ((unsigned long long)vmax << 32) | (uint32_t)(~imin);
            unsigned long long xyp;
            asm("mov.b64 %0, {%1, %2};" : "=l"(xyp) : "f"(cx), "f"(cy));
            const uint32_t zb = __float_as_uint(cz);
            const uint32_t ka = smem_u32(&s_key[p][myslot]);
            const uint32_t ca = smem_u32(&s_co[p][myslot]);
            const int dco = (int)(ca - ka);
            uint32_t rk;
            asm volatile("mapa.shared::cluster.u32 %0, %1, %2;"
                         : "=r"(rk) : "r"(ka), "r"(l));
            asm volatile("st.shared::cluster.b64 [%0], %1;"
                         :: "r"(rk), "l"(key) : "memory");
            asm volatile("st.shared::cluster.b64 [%0], %1;"
                         :: "r"(rk + dco), "l"(xyp) : "memory");
            asm volatile("st.shared::cluster.b32 [%0+8], %1;"
                         :: "r"(rk + dco), "r"(zb) : "memory");
        }

        // arrive = release (orders the remote stores), wait = acquire.
        // This is the ONLY synchronization in the loop (also CTA-internal).
        asm volatile("barrier.cluster.arrive.aligned;" ::: "memory");
        asm volatile("barrier.cluster.wait.aligned;" ::: "memory");

        // ---- warp-parallel pick over the 32 cluster candidates ----
        {
            uint32_t klo, khi;
            {
                const unsigned long long kk = s_key[p][l];
                asm("mov.b64 {%0, %1}, %2;" : "=r"(klo), "=r"(khi) : "l"(kk));
            }
            const uint32_t vm = __reduce_max_sync(0xffffffffu, khi);
            const uint32_t ix = ~klo;                 // original index
            const uint32_t im = __reduce_min_sync(0xffffffffu,
                                    (khi == vm) ? ix : 0xffffffffu);
            const uint32_t win = __ballot_sync(0xffffffffu,
                                    (khi == vm) && (ix == im));
            const int wslot = __ffs(win) - 1;         // exactly one bit set
            const float4 co = s_co[p][wslot];          // broadcast LDS.128
            lx = co.x; ly = co.y; lz = co.z;
        }

        if (rank == 0 && tid == 0) {
            ob[j]              = lx;
            ob[NPOINT + j]     = ly;
            ob[2 * NPOINT + j] = lz;
        }
    }

    // no CTA may exit while peers may still target its smem
    asm volatile("barrier.cluster.arrive.aligned;" ::: "memory");
    asm volatile("barrier.cluster.wait.aligned;" ::: "memory");
}

extern "C" void kernel_launch(void* const* d_in, const int* in_sizes, int n_in,
                              void* d_out, int out_size)
{
    (void)in_sizes; (void)n_in; (void)out_size;
    const float* xyz_t = (const float*)d_in[1];   // points_xyz_t: (B, 3, N)
    float* out = (float*)d_out;                   // (B, 3, NPOINT)

    // Opt in to >48KB-total smem (48KB dynamic + ~1.5KB static). Host-side
    // attribute call: nothing enqueued on the stream, capture-safe,
    // deterministic and idempotent.
    const int dyn_bytes = 3 * PER_CTA * (int)sizeof(float);   // 49152
    cudaFuncSetAttribute(fps_cluster_kernel,
                         cudaFuncAttributeMaxDynamicSharedMemorySize, dyn_bytes);

    fps_cluster_kernel<<<BATCH * CLUSTER, T, dyn_bytes>>>(xyz_t, out);
}

// round 14
// speedup vs baseline: 1.4523x; 1.0138x over previous
#include <cuda_runtime.h>
#include <cstdint>

// D-FPS (B=8, N=32768, npoint=2048) + gather xyz -> out (B,3,2048) fp32.
//
// One 8-CTA cluster per batch (64 CTAs, 128 threads = 4 warps). Each thread
// owns 32 points, PACKED f32x2 in registers; running-min temp in registers.
// Per iteration:
//   - packed add/mul.rn.f32x2 distance update (per-lane .rn => bit-exact)
//   - thread-local argmax split into 4 INDEPENDENT accumulator chains over
//     contiguous quarters (serial dependency depth 32 -> 8+3), merged in
//     ascending order with strict '>' => first-occurrence ties preserved
//   - warp argmax via redux.sync (float bits of v>=0 are u32-monotone),
//     min-index tie-break == jnp.argmax first-occurrence
//   - CTA argmax in warp0 via redux over 4 warp candidates; lanes 0..7 push
//     {key,x,y,z} to cluster CTA dst==lane in parallel (mapa +
//     st.shared::cluster); winner coords from CTA-local smem table (LDS)
//   - ONE barrier.cluster (arrive releases the remote stores, wait acquires)
//   - every thread picks the cluster winner from its own smem slots.
// Slots double-buffered by parity: a same-parity overwrite for iter j+2 can
// only be issued after the cluster barrier of iter j+1, which post-dates all
// reads of the iter-j slots.

constexpr int BATCH   = 8;
constexpr int NPTS    = 32768;
constexpr int NPOINT  = 2048;
constexpr int CLUSTER = 8;
constexpr int T       = 128;
constexpr int PER_CTA = NPTS / CLUSTER;  // 4096
constexpr int P       = PER_CTA / T;     // 32 points / thread
constexpr int NPAIR   = P / 2;           // 16 packed pairs
constexpr int NW      = T / 32;          // 4 warps

__device__ __forceinline__ uint32_t smem_u32(const void* p) {
    uint32_t a;
    asm("{ .reg .u64 t; cvta.to.shared.u64 t, %1; cvt.u32.u64 %0, t; }"
        : "=r"(a) : "l"(p));
    return a;
}

extern __shared__ float s_dyn[];  // sx[4096] | sy[4096] | sz[4096] = 48KB

__global__ __launch_bounds__(T, 1) __cluster_dims__(CLUSTER, 1, 1)
void fps_cluster_kernel(const float* __restrict__ xyz_t, float* __restrict__ out)
{
    const int b = blockIdx.x >> 3;
    uint32_t rank;
    asm("mov.u32 %0, %%cluster_ctarank;" : "=r"(rank));

    const float* __restrict__ xs = xyz_t + (size_t)b * 3 * NPTS;
    const float* __restrict__ ys = xs + NPTS;
    const float* __restrict__ zs = xs + 2 * NPTS;
    float* __restrict__ ob = out + (size_t)b * 3 * NPOINT;

    const int tid = threadIdx.x;
    const int w = tid >> 5, l = tid & 31;
    const int pbase = (int)rank * PER_CTA;

    float* sx = s_dyn;
    float* sy = s_dyn + PER_CTA;
    float* sz = s_dyn + 2 * PER_CTA;

    __shared__ uint32_t s_wv[NW], s_wi[NW];
    __shared__ unsigned long long s_key[2][CLUSTER];
    __shared__ float4 s_co[2][CLUSTER];

    // ---- load coords: smem table + packed registers ----
    unsigned long long xp[NPAIR], yp[NPAIR], zp[NPAIR];
    float tmp[P];
#pragma unroll
    for (int q = 0; q < NPAIR; ++q) {
        const int g0 = pbase + (2 * q)     * T + tid;
        const int g1 = pbase + (2 * q + 1) * T + tid;
        const float ax0 = xs[g0], ax1 = xs[g1];
        const float ay0 = ys[g0], ay1 = ys[g1];
        const float az0 = zs[g0], az1 = zs[g1];
        sx[(2*q)   * T + tid] = ax0;  sx[(2*q+1) * T + tid] = ax1;
        sy[(2*q)   * T + tid] = ay0;  sy[(2*q+1) * T + tid] = ay1;
        sz[(2*q)   * T + tid] = az0;  sz[(2*q+1) * T + tid] = az1;
        asm("mov.b64 %0, {%1, %2};" : "=l"(xp[q]) : "f"(ax0), "f"(ax1));
        asm("mov.b64 %0, {%1, %2};" : "=l"(yp[q]) : "f"(ay0), "f"(ay1));
        asm("mov.b64 %0, {%1, %2};" : "=l"(zp[q]) : "f"(az0), "f"(az1));
        tmp[2*q] = 1e10f; tmp[2*q+1] = 1e10f;
    }

    float lx = __ldg(xs), ly = __ldg(ys), lz = __ldg(zs);  // idx[0] = 0
    if (rank == 0 && tid == 0) {
        ob[0] = lx; ob[NPOINT] = ly; ob[2 * NPOINT] = lz;
    }

    for (int j = 1; j < NPOINT; ++j) {
        // packed negated center (per-lane duplicate)
        unsigned long long nlx2, nly2, nlz2;
        {
            const float nx = -lx, ny = -ly, nz = -lz;
            asm("mov.b64 %0, {%1, %1};" : "=l"(nlx2) : "f"(nx));
            asm("mov.b64 %0, {%1, %1};" : "=l"(nly2) : "f"(ny));
            asm("mov.b64 %0, {%1, %1};" : "=l"(nlz2) : "f"(nz));
        }

        // 4 independent argmax chains over contiguous quarters -> short
        // dependency chains; ascending merge preserves first-occurrence.
        float bvs[4] = {-1.0f, -1.0f, -1.0f, -1.0f};
        int   bss[4] = {0, 0, 0, 0};
#pragma unroll
        for (int q = 0; q < NPAIR; ++q) {
            const int c = q >> 2;   // chain id; slots [8c, 8c+8)
            unsigned long long dx, dy, dz, qx, qy, qz, s01, acc;
            asm("add.rn.f32x2 %0, %1, %2;" : "=l"(dx) : "l"(xp[q]), "l"(nlx2));
            asm("add.rn.f32x2 %0, %1, %2;" : "=l"(dy) : "l"(yp[q]), "l"(nly2));
            asm("add.rn.f32x2 %0, %1, %2;" : "=l"(dz) : "l"(zp[q]), "l"(nlz2));
            asm("mul.rn.f32x2 %0, %1, %1;" : "=l"(qx) : "l"(dx));
            asm("mul.rn.f32x2 %0, %1, %1;" : "=l"(qy) : "l"(dy));
            asm("mul.rn.f32x2 %0, %1, %1;" : "=l"(qz) : "l"(dz));
            asm("add.rn.f32x2 %0, %1, %2;" : "=l"(s01) : "l"(qx), "l"(qy));
            asm("add.rn.f32x2 %0, %1, %2;" : "=l"(acc) : "l"(s01), "l"(qz));
            float d0, d1;
            asm("mov.b64 {%0, %1}, %2;" : "=f"(d0), "=f"(d1) : "l"(acc));
            float t0 = fminf(tmp[2*q], d0);     tmp[2*q] = t0;
            if (t0 > bvs[c]) { bvs[c] = t0; bss[c] = 2*q; }
            float t1 = fminf(tmp[2*q+1], d1);   tmp[2*q+1] = t1;
            if (t1 > bvs[c]) { bvs[c] = t1; bss[c] = 2*q+1; }
        }
        float bv = bvs[0];
        int   bs = bss[0];
        if (bvs[1] > bv) { bv = bvs[1]; bs = bss[1]; }
        if (bvs[2] > bv) { bv = bvs[2]; bs = bss[2]; }
        if (bvs[3] > bv) { bv = bvs[3]; bs = bss[3]; }
        const uint32_t idx = (uint32_t)(pbase + bs * T + tid);

        // ---- warp argmax via redux (float bits of v>=0 are u32-monotone) ----
        const uint32_t vb   = __float_as_uint(bv);
        const uint32_t vmax = __reduce_max_sync(0xffffffffu, vb);
        const uint32_t imin = __reduce_min_sync(0xffffffffu,
                                   (vb == vmax) ? idx : 0xffffffffu);
        if (l == 0) { s_wv[w] = vmax; s_wi[w] = imin; }
        __syncthreads();

        const int p = j & 1;

        if (w == 0) {
            const uint32_t v  = (l < NW) ? s_wv[l] : 0u;
            const uint32_t ii = (l < NW) ? s_wi[l] : 0xffffffffu;
            const uint32_t vm = __reduce_max_sync(0xffffffffu, v);
            const uint32_t im = __reduce_min_sync(0xffffffffu,
                                    (v == vm) ? ii : 0xffffffffu);
            // redux leaves the result in every lane: lanes 0..7 disseminate
            // to cluster CTA dst == lane, in parallel.
            if (l < CLUSTER) {
                const int li = (int)im - pbase;      // winner is in own range
                const float cx = sx[li], cy = sy[li], cz = sz[li];  // LDS bcast
                const unsigned long long key =
                    ((unsigned long long)vm << 32) | (uint32_t)(~im);
                unsigned long long xyp;
                asm("mov.b64 %0, {%1, %2};" : "=l"(xyp) : "f"(cx), "f"(cy));
                const uint32_t zb = __float_as_uint(cz);
                const uint32_t ka = smem_u32(&s_key[p][rank]);
                const uint32_t ca = smem_u32(&s_co[p][rank]);
                const int dco = (int)(ca - ka);
                uint32_t rk;
                asm volatile("mapa.shared::cluster.u32 %0, %1, %2;"
                             : "=r"(rk) : "r"(ka), "r"(l));
                asm volatile("st.shared::cluster.b64 [%0], %1;"
                             :: "r"(rk), "l"(key) : "memory");
                asm volatile("st.shared::cluster.b64 [%0], %1;"
                             :: "r"(rk + dco), "l"(xyp) : "memory");
                asm volatile("st.shared::cluster.b32 [%0+8], %1;"
                             :: "r"(rk + dco), "r"(zb) : "memory");
            }
        }

        // arrive = release (orders the shared::cluster stores), wait = acquire
        asm volatile("barrier.cluster.arrive.aligned;" ::: "memory");
        asm volatile("barrier.cluster.wait.aligned;" ::: "memory");

        // ---- every thread picks the cluster winner locally ----
        unsigned long long wk = s_key[p][0];
        int wc = 0;
#pragma unroll
        for (int c = 1; c < CLUSTER; ++c) {
            const unsigned long long kk = s_key[p][c];
            if (kk > wk) { wk = kk; wc = c; }
        }
        const float4 co = s_co[p][wc];
        lx = co.x; ly = co.y; lz = co.z;

        if (rank == 0 && tid == 0) {
            ob[j]              = lx;
            ob[NPOINT + j]     = ly;
            ob[2 * NPOINT + j] = lz;
        }
    }
}

extern "C" void kernel_launch(void* const* d_in, const int* in_sizes, int n_in,
                              void* d_out, int out_size)
{
    (void)in_sizes; (void)n_in; (void)out_size;
    const float* xyz_t = (const float*)d_in[1];   // points_xyz_t: (B, 3, N)
    float* out = (float*)d_out;                   // (B, 3, NPOINT)

    // Opt in to >48KB-total smem (48KB dynamic + ~0.3KB static). Host-side
    // attribute call: nothing enqueued on the stream, capture-safe,
    // deterministic and idempotent.
    const int dyn_bytes = 3 * PER_CTA * (int)sizeof(float);   // 49152
    cudaFuncSetAttribute(fps_cluster_kernel,
                         cudaFuncAttributeMaxDynamicSharedMemorySize, dyn_bytes);

    fps_cluster_kernel<<<BATCH * CLUSTER, T, dyn_bytes>>>(xyz_t, out);
}